// round 14
// baseline (speedup 1.0000x reference)
#include <cuda_runtime.h>
#include <cstddef>

#define Bn 8
#define Cn 4
#define Hn 768
#define Wn 768
#define Rr 8
#define NCH 19
#define EPSc 1e-4f

// A-sum and b intermediate (only 2 channels survive stage 1)
__device__ float g_Ab[(size_t)2 * Bn * Hn * Wn];

// channel -> (planeA, planeB); plane 4 = p, 0..3 = I_c. ch 0..4 identity.
__constant__ int c_pA[NCH] = {0,1,2,3, 4, 4,4,4,4, 0,0,0,0,1,1,1,2,2,3};
__constant__ int c_pB[NCH] = {0,1,2,3, 4, 0,1,2,3, 0,1,2,3,1,2,3,2,3,3};

__device__ __forceinline__ int wcnt(int t, int L) {
    int lo = t - Rr; if (lo < 0) lo = 0;
    int hi = t + Rr; if (hi > L - 1) hi = L - 1;
    return hi - lo + 1;
}

__device__ __forceinline__ float frcp(float x) {
    float r;
    asm("rcp.approx.f32 %0, %1;" : "=f"(r) : "f"(x));
    return r;
}

// ---------------------------------------------------------------------------
// Stage 1: vertical ring-buffer strip kernel.
// Block = 32-wide x 96-tall output strip, 8 steps of 12 rows.
// hs ring = 28 ext-rows (phys = lr mod 28).
// P1 task = (channel, row): one channel over full 32-px row, sliding window.
// Identity channels multiply by an SMEM "ones" row (broadcast LDS).
// SMEM (floats):
//   hs   [0, 17556)      : 19 ch x 28 ring rows x 33
//   outb [17556, 24852)  : 19 x 12 x 32 = 7296  (also step-0 raw: 5x28x49=6860)
//   rawb [24852, 27792)  : 5 x 12 x 49 = 2940   (steady-state raw)
//   ones [27792, 27844)  : 52 floats (49 used)
// total 27844 floats = 111376 B -> 2 CTAs/SM.
// ---------------------------------------------------------------------------
#define T1W 32
#define HSTEP 12
#define NSTEP 8
#define RING 28
#define RPW 49
#define HP1 33
#define HCH (RING * HP1)            // 924
#define SZ1_HS  (NCH * HCH)         // 17556
#define SZ1_OUT (NCH * HSTEP * T1W) // 7296
#define SZ1_RAW (5 * HSTEP * RPW)   // 2940
#define SMEM1_BYTES ((SZ1_HS + SZ1_OUT + SZ1_RAW + 52) * 4)  // 111376

__device__ __forceinline__ float4 load_halo4(const float* __restrict__ src,
                                             int gy, int gx0, bool intx) {
    float4 v = make_float4(0.f, 0.f, 0.f, 0.f);
    if ((unsigned)gy < (unsigned)Hn) {
        if (intx) {
            v = *reinterpret_cast<const float4*>(src + (size_t)gy * Wn + gx0);
        } else {
            const float* r = src + (size_t)gy * Wn;
            if ((unsigned)(gx0 + 0) < (unsigned)Wn) v.x = r[gx0 + 0];
            if ((unsigned)(gx0 + 1) < (unsigned)Wn) v.y = r[gx0 + 1];
            if ((unsigned)(gx0 + 2) < (unsigned)Wn) v.z = r[gx0 + 2];
            if ((unsigned)(gx0 + 3) < (unsigned)Wn) v.w = r[gx0 + 3];
        }
    }
    return v;
}

// One-channel horizontal 17-tap box over full 32-px row (sliding window).
__device__ __forceinline__ void p1_row(const float* __restrict__ ra,
                                       const float* __restrict__ rb,
                                       float* __restrict__ hrow) {
    float s = 0.f;
#pragma unroll
    for (int i = 0; i < 17; i++) s = fmaf(ra[i], rb[i], s);
    hrow[0] = s;
#pragma unroll
    for (int j = 1; j < T1W; j++) {
        s = fmaf(ra[j + 16], rb[j + 16], s);
        s = fmaf(-ra[j - 1], rb[j - 1], s);
        hrow[j] = s;
    }
}

__global__ __launch_bounds__(512, 2) void k_stage1(const float* __restrict__ I,
                                                   const float* __restrict__ p) {
    extern __shared__ float sm[];
    float* hs   = sm;
    float* outb = sm + SZ1_HS;
    float* rawb = sm + SZ1_HS + SZ1_OUT;
    float* ones = sm + SZ1_HS + SZ1_OUT + SZ1_RAW;

    int b  = blockIdx.z;
    int X0 = blockIdx.x * T1W;
    int Y0 = blockIdx.y * (HSTEP * NSTEP);     // 96-row group
    int tid = threadIdx.x;
    const size_t HW = (size_t)Hn * Wn;
    const size_t PL = (size_t)Bn * Hn * Wn;
    bool intx = (X0 >= Rr) && (X0 + T1W + Rr <= Wn);

    if (tid < RPW) ones[tid] = 1.0f;

    // persistent P2 state (vertical running sums; all tasks share row sequence)
    float S0 = 0.f, S1 = 0.f;
    int leadp = 0, trailp = 0;
    int ch0 = tid >> 5, col0 = tid & 31;
    int ch1 = 16 + (tid >> 5);          // task tid+512 (valid when tid < 96)
    bool dual = (tid < 96);

    for (int s = 0; s < NSTEP; s++) {
        if (s == 0) {
            // ---- P0big: load ext rows lr 0..27 into outb (raw28) ----
            for (int i = tid; i < 5 * RING * 12; i += 512) {
                int pl  = i / (RING * 12);
                int rem = i - pl * (RING * 12);
                int lr  = rem / 12;
                int ex4 = rem - lr * 12;
                const float* src = (pl < 4) ? I + ((size_t)b * Cn + pl) * HW
                                            : p + (size_t)b * HW;
                float4 v = load_halo4(src, Y0 - 8 + lr, X0 - 8 + ex4 * 4, intx);
                float* d = outb + (pl * RING + lr) * RPW + ex4 * 4;
                d[0] = v.x; d[1] = v.y; d[2] = v.z; d[3] = v.w;
            }
            __syncthreads();
            // ---- P1big: 532 tasks = (ch 0..18, row 0..27), phys = lr ----
            for (int t = tid; t < NCH * RING; t += 512) {
                int ch = t / RING;
                int rl = t - ch * RING;
                const float* ra = outb + (c_pA[ch] * RING + rl) * RPW;
                const float* rb = (ch < 5) ? ones
                                           : outb + (c_pB[ch] * RING + rl) * RPW;
                p1_row(ra, rb, hs + ch * HCH + rl * HP1);
            }
            __syncthreads();
        } else {
            // ---- P1 steady: 228 tasks = (ch 0..18, row 0..11) ----
            if (tid < NCH * HSTEP) {
                int ch = tid / HSTEP;
                int rl = tid - ch * HSTEP;
                int lr = 12 * s + 16 + rl;
                int phys = lr % RING;
                const float* ra = rawb + (c_pA[ch] * HSTEP + rl) * RPW;
                const float* rb = (ch < 5) ? ones
                                           : rawb + (c_pB[ch] * HSTEP + rl) * RPW;
                p1_row(ra, rb, hs + ch * HCH + phys * HP1);
            }
            __syncthreads();
        }

        // ---- Phase C: prefetch next raw (regs) + P2 vertical slide ----
        float4 pv0, pv1;
        int st0 = -1, st1 = -1;
        if (s < NSTEP - 1) {
            int ns = s + 1;
            {
                int i = tid;                 // task 0..511
                int pl  = i / 144;
                int rem = i - pl * 144;
                int lrl = rem / 12;
                int ex4 = rem - lrl * 12;
                int lr  = 12 * ns + 16 + lrl;
                const float* src = (pl < 4) ? I + ((size_t)b * Cn + pl) * HW
                                            : p + (size_t)b * HW;
                pv0 = load_halo4(src, Y0 - 8 + lr, X0 - 8 + ex4 * 4, intx);
                st0 = (pl * HSTEP + lrl) * RPW + ex4 * 4;
            }
            int i1 = tid + 512;
            if (i1 < 720) {                  // tasks 512..719
                int pl  = i1 / 144;
                int rem = i1 - pl * 144;
                int lrl = rem / 12;
                int ex4 = rem - lrl * 12;
                int lr  = 12 * ns + 16 + lrl;
                const float* src = (pl < 4) ? I + ((size_t)b * Cn + pl) * HW
                                            : p + (size_t)b * HW;
                pv1 = load_halo4(src, Y0 - 8 + lr, X0 - 8 + ex4 * 4, intx);
                st1 = (pl * HSTEP + lrl) * RPW + ex4 * 4;
            }
        }

        // P2: add lead rows; emit outputs; subtract trail rows.
        {
            int nIt = (s == 0) ? (16 + HSTEP) : HSTEP;   // 16 silent adds at s=0
            int yoff = (s == 0) ? -16 : 0;
            for (int k = 0; k < nIt; k++) {
                S0 += hs[ch0 * HCH + leadp * HP1 + col0];
                if (dual) S1 += hs[ch1 * HCH + leadp * HP1 + col0];
                leadp++; if (leadp == RING) leadp = 0;
                int y = k + yoff;
                if (y >= 0) {
                    outb[(ch0 * HSTEP + y) * T1W + col0] = S0;
                    if (dual) outb[(ch1 * HSTEP + y) * T1W + col0] = S1;
                    S0 -= hs[ch0 * HCH + trailp * HP1 + col0];
                    if (dual) S1 -= hs[ch1 * HCH + trailp * HP1 + col0];
                    trailp++; if (trailp == RING) trailp = 0;
                }
            }
        }

        // store prefetched raw rows
        if (st0 >= 0) {
            float* d = rawb + st0;
            d[0] = pv0.x; d[1] = pv0.y; d[2] = pv0.z; d[3] = pv0.w;
        }
        if (st1 >= 0) {
            float* d = rawb + st1;
            d[0] = pv1.x; d[1] = pv1.y; d[2] = pv1.z; d[3] = pv1.w;
        }
        __syncthreads();

        // ---- P3: per-pixel 4x4 SPD solve  M x = 1  (384 px) ----
        if (tid < HSTEP * T1W) {
            int x = tid & 31, y = tid >> 5;
            int gy = Y0 + 12 * s + y;
            int gx = X0 + x;
            float invN = frcp((float)(wcnt(gx, Wn) * wcnt(gy, Hn)));

            float S[NCH];
#pragma unroll
            for (int c = 0; c < NCH; c++) S[c] = outb[(c * HSTEP + y) * T1W + x];

            float m0 = S[0] * invN, m1 = S[1] * invN, m2 = S[2] * invN, m3 = S[3] * invN;
            float pm = S[4] * invN;
            float ip0 = S[5] * invN, ip1 = S[6] * invN, ip2 = S[7] * invN, ip3 = S[8] * invN;

            float Mm[4][4];
            Mm[0][0] = S[9]  * invN + EPSc;
            Mm[0][1] = Mm[1][0] = S[10] * invN;
            Mm[0][2] = Mm[2][0] = S[11] * invN;
            Mm[0][3] = Mm[3][0] = S[12] * invN;
            Mm[1][1] = S[13] * invN + EPSc;
            Mm[1][2] = Mm[2][1] = S[14] * invN;
            Mm[1][3] = Mm[3][1] = S[15] * invN;
            Mm[2][2] = S[16] * invN + EPSc;
            Mm[2][3] = Mm[3][2] = S[17] * invN;
            Mm[3][3] = S[18] * invN + EPSc;

            float xv[4] = {1.f, 1.f, 1.f, 1.f};
#pragma unroll
            for (int kk = 0; kk < 4; kk++) {
                float inv = frcp(Mm[kk][kk]);
#pragma unroll
                for (int j = 0; j < 4; j++) if (j > kk) Mm[kk][j] *= inv;
                xv[kk] *= inv;
#pragma unroll
                for (int i = 0; i < 4; i++) if (i > kk) {
                    float f = Mm[i][kk];
#pragma unroll
                    for (int j = 0; j < 4; j++) if (j > kk) Mm[i][j] -= f * Mm[kk][j];
                    xv[i] -= f * xv[kk];
                }
            }
#pragma unroll
            for (int kk = 2; kk >= 0; kk--) {
#pragma unroll
                for (int j = 0; j < 4; j++) if (j > kk) xv[kk] -= Mm[kk][j] * xv[j];
            }

            float ft0 = ip0 - pm * m0;
            float ft1 = ip1 - pm * m1;
            float ft2 = ip2 - pm * m2;
            float ft3 = ip3 - pm * m3;
            float Asum = ft0 * xv[0] + ft1 * xv[1] + ft2 * xv[2] + ft3 * xv[3];
            float msum = m0 + m1 + m2 + m3;
            float bv   = pm - Asum * msum;

            size_t pix = ((size_t)b * Hn + gy) * Wn + gx;
            g_Ab[pix] = Asum;
            g_Ab[PL + pix] = bv;
        }
        __syncthreads();
    }
}

// ---------------------------------------------------------------------------
// Stage 2: fused 2D box of (Asum, b) + final combine. (unchanged, ~50us)
// ---------------------------------------------------------------------------
#define T2 64
#define E2 80
#define RP2 81
#define HP2 65
#define SZ2_RAW (2 * E2 * RP2)
#define SZ2_HS  (2 * E2 * HP2)
#define SMEM2_BYTES ((SZ2_RAW + SZ2_HS) * 4)
#define YSEG 8

__global__ __launch_bounds__(512) void k_stage2(const float* __restrict__ I,
                                                float* __restrict__ q) {
    extern __shared__ float sm[];
    float* raw = sm;
    float* hsb = sm + SZ2_RAW;

    int b  = blockIdx.z;
    int X0 = blockIdx.x * T2, Y0 = blockIdx.y * T2;
    int tid = threadIdx.x;
    const size_t PL = (size_t)Bn * Hn * Wn;

    {
        bool intx = (X0 >= Rr) && (X0 + T2 + Rr <= Wn);
        for (int i = tid; i < 2 * E2 * 20; i += 512) {
            int pl  = i / (E2 * 20);
            int rem = i - pl * (E2 * 20);
            int ey  = rem / 20;
            int ex4 = rem - ey * 20;
            int gy  = Y0 - Rr + ey;
            int gx0 = X0 - Rr + ex4 * 4;
            const float* src = g_Ab + (size_t)pl * PL + (size_t)b * Hn * Wn;
            float4 v = load_halo4(src, gy, gx0, intx);
            float* d = raw + (pl * E2 + ey) * RP2 + ex4 * 4;
            d[0] = v.x; d[1] = v.y; d[2] = v.z; d[3] = v.w;
        }
    }
    __syncthreads();

    for (int t = tid; t < 2 * E2 * 4; t += 512) {
        int ch  = (t >= E2 * 4) ? 1 : 0;
        int rem = t - ch * E2 * 4;
        int ey  = rem >> 2;
        int x0  = (rem & 3) << 4;
        const float* ra = raw + (ch * E2 + ey) * RP2 + x0;
        float s = 0.f;
#pragma unroll
        for (int i = 0; i < 17; i++) s += ra[i];
        float* hrow = hsb + (ch * E2 + ey) * HP2 + x0;
        hrow[0] = s;
#pragma unroll
        for (int x = 1; x < 16; x++) {
            s += ra[x + 16] - ra[x - 1];
            hrow[x] = s;
        }
    }
    __syncthreads();

    {
        int col = tid & 63;
        int seg = tid >> 6;
        int ys  = seg * YSEG;
        const float* hA = hsb + col;
        const float* hB = hsb + (size_t)E2 * HP2 + col;

        float SA = 0.f, SB = 0.f;
#pragma unroll
        for (int j = 0; j < 17; j++) {
            SA += hA[(ys + j) * HP2];
            SB += hB[(ys + j) * HP2];
        }
        int gx = X0 + col;
        int cntx = wcnt(gx, Wn);
        const float* Ib = I + ((size_t)b * Cn) * Hn * Wn;

#pragma unroll
        for (int yy = 0; yy < YSEG; yy++) {
            int gy = Y0 + ys + yy;
            float invN = frcp((float)(wcnt(gy, Hn) * cntx));
            size_t row = (size_t)gy * Wn + gx;
            float isum = Ib[row]
                       + Ib[(size_t)Hn * Wn + row]
                       + Ib[(size_t)2 * Hn * Wn + row]
                       + Ib[(size_t)3 * Hn * Wn + row];
            q[((size_t)b * Hn + gy) * Wn + gx] = (SA * invN) * isum + SB * invN;

            if (yy < YSEG - 1) {
                int lead = ys + yy + 17, trail = ys + yy;
                SA += hA[lead * HP2] - hA[trail * HP2];
                SB += hB[lead * HP2] - hB[trail * HP2];
            }
        }
    }
}

extern "C" void kernel_launch(void* const* d_in, const int* in_sizes, int n_in,
                              void* d_out, int out_size) {
    const float* I = (const float*)d_in[0];
    const float* p = (const float*)d_in[1];
    float* q = (float*)d_out;

    static bool attr_done = false;
    if (!attr_done) {
        cudaFuncSetAttribute(k_stage1, cudaFuncAttributeMaxDynamicSharedMemorySize, SMEM1_BYTES);
        cudaFuncSetAttribute(k_stage2, cudaFuncAttributeMaxDynamicSharedMemorySize, SMEM2_BYTES);
        attr_done = true;
    }

    k_stage1<<<dim3(Wn / T1W, Hn / (HSTEP * NSTEP), Bn), 512, SMEM1_BYTES>>>(I, p);
    k_stage2<<<dim3(Wn / T2, Hn / T2, Bn), 512, SMEM2_BYTES>>>(I, q);
}